// round 1
// baseline (speedup 1.0000x reference)
#include <cuda_runtime.h>
#include <cuda_bf16.h>
#include <math.h>

// Problem constants
#define NB   32      // batch
#define TT   2048    // time steps
#define DD   1024    // D_ENC = D_DEC = U

// GEMM tiling for k_weights
#define BT 128       // t rows per block
#define BU 128       // u cols per block
#define KT 16        // k slice per stage
#define NUB (DD/BU)  // 8 u-tiles

// Scratch (no allocation allowed -> device globals)
__device__ float g_pq[NB * DD];               // 128 KB
__device__ float g_wpart[NUB * NB * TT];      // 2 MB  (per-u-tile logit partials)
__device__ float g_ctxpart[4 * NB * DD];      // 512 KB (t-split context partials)

// ---------------------------------------------------------------------------
// K1: pq[n,u] = sum_k q[n,k] * Wq[u,k]
// grid (NB, 4), 256 threads. Warp-per-u with coalesced Wq reads.
// ---------------------------------------------------------------------------
__global__ void k_pq(const float* __restrict__ q, const float* __restrict__ Wq)
{
    int n = blockIdx.x;
    __shared__ float sq[DD];
    int tid = threadIdx.x;
    for (int i = tid; i < DD; i += 256) sq[i] = q[n * DD + i];
    __syncthreads();

    int warp = tid >> 5, lane = tid & 31;
    int ubase = blockIdx.y * 256 + warp * 32;
    for (int uu = 0; uu < 32; uu++) {
        int u = ubase + uu;
        const float* wr = Wq + (size_t)u * DD;
        float s = 0.f;
        #pragma unroll 8
        for (int m = 0; m < 32; m++)
            s = fmaf(sq[lane + 32 * m], wr[lane + 32 * m], s);
        #pragma unroll
        for (int off = 16; off; off >>= 1)
            s += __shfl_xor_sync(0xffffffffu, s, off);
        if (lane == 0) g_pq[n * DD + u] = s;
    }
}

// ---------------------------------------------------------------------------
// K2: for u-tile ub: wpart[ub][n][t] = sum_{u in tile} tanh(pq[n,u] + enc[n,t,:].Wk[u,:]) * v[u]
// 128x128 block tile, 8x8 per thread, K staged 16 at a time in smem.
// Skips t-tiles fully beyond lengths[n].
// grid (TT/BT=16, NB=32, NUB=8), 256 threads.
// ---------------------------------------------------------------------------
__global__ __launch_bounds__(256, 2)
void k_weights(const float* __restrict__ enc, const float* __restrict__ Wk,
               const float* __restrict__ v, const int* __restrict__ lengths)
{
    int tb = blockIdx.x;
    int n  = blockIdx.y;
    int ub = blockIdx.z;
    int len = lengths[n];
    int t0 = tb * BT;
    if (t0 >= len) return;   // uniform per block

    __shared__ float sE[KT][BT];   // [k][t]
    __shared__ float sW[KT][BU];   // [k][u]

    int tid = threadIdx.x;
    int tx = tid & 15;   // u dim (16)
    int ty = tid >> 4;   // t dim (16)

    float acc[8][8];
    #pragma unroll
    for (int i = 0; i < 8; i++)
        #pragma unroll
        for (int j = 0; j < 8; j++) acc[i][j] = 0.f;

    const float* encb = enc + ((size_t)n * TT + t0) * DD;
    const float* wkb  = Wk + (size_t)ub * BU * DD;

    for (int ks = 0; ks < DD; ks += KT) {
        // cooperative load: 2 float4 per thread per matrix
        #pragma unroll
        for (int r = 0; r < 2; r++) {
            int f  = tid + r * 256;          // 0..511
            int rw = f >> 2;                 // row (t or u), 0..127
            int kq = (f & 3) * 4;            // k quad base, 0/4/8/12
            float4 e4 = *(const float4*)(encb + (size_t)rw * DD + ks + kq);
            sE[kq + 0][rw] = e4.x; sE[kq + 1][rw] = e4.y;
            sE[kq + 2][rw] = e4.z; sE[kq + 3][rw] = e4.w;
            float4 w4 = *(const float4*)(wkb + (size_t)rw * DD + ks + kq);
            sW[kq + 0][rw] = w4.x; sW[kq + 1][rw] = w4.y;
            sW[kq + 2][rw] = w4.z; sW[kq + 3][rw] = w4.w;
        }
        __syncthreads();

        #pragma unroll
        for (int k = 0; k < KT; k++) {
            float a[8], b[8];
            *(float4*)&a[0] = *(const float4*)&sE[k][ty * 8];
            *(float4*)&a[4] = *(const float4*)&sE[k][ty * 8 + 4];
            *(float4*)&b[0] = *(const float4*)&sW[k][tx * 8];
            *(float4*)&b[4] = *(const float4*)&sW[k][tx * 8 + 4];
            #pragma unroll
            for (int i = 0; i < 8; i++)
                #pragma unroll
                for (int j = 0; j < 8; j++)
                    acc[i][j] = fmaf(a[i], b[j], acc[i][j]);
        }
        __syncthreads();
    }

    // epilogue: tanh(acc + pq) * v, reduce over u within the tile
    int u0 = ub * BU + tx * 8;
    float pqv[8], vv[8];
    #pragma unroll
    for (int j = 0; j < 8; j++) {
        pqv[j] = __ldg(&g_pq[n * DD + u0 + j]);
        vv[j]  = __ldg(&v[u0 + j]);
    }
    float wsum[8];
    #pragma unroll
    for (int i = 0; i < 8; i++) {
        float s = 0.f;
        #pragma unroll
        for (int j = 0; j < 8; j++)
            s = fmaf(tanhf(acc[i][j] + pqv[j]), vv[j], s);
        wsum[i] = s;
    }
    // reduce across tx (16-lane groups within the warp)
    #pragma unroll
    for (int m = 8; m; m >>= 1)
        #pragma unroll
        for (int i = 0; i < 8; i++)
            wsum[i] += __shfl_xor_sync(0xffffffffu, wsum[i], m);

    if (tx == 0) {
        #pragma unroll
        for (int i = 0; i < 8; i++) {
            int t = t0 + ty * 8 + i;
            g_wpart[((size_t)ub * NB + n) * TT + t] = wsum[i];
        }
    }
}

// ---------------------------------------------------------------------------
// K3: sum u-tile partials, mask, stable softmax -> alignments (d_out tail)
// grid NB, 256 threads (8 t's per thread)
// ---------------------------------------------------------------------------
__global__ void k_softmax(const int* __restrict__ lengths, float* __restrict__ align)
{
    int n = blockIdx.x, tid = threadIdx.x;
    int len = lengths[n];
    int warp = tid >> 5, lane = tid & 31;
    __shared__ float sred[8];

    float w[8];
    float mx = -INFINITY;
    #pragma unroll
    for (int r = 0; r < 8; r++) {
        int t = r * 256 + tid;
        float s;
        if (t < len) {
            s = 0.f;
            #pragma unroll
            for (int p = 0; p < NUB; p++)
                s += g_wpart[((size_t)p * NB + n) * TT + t];
        } else {
            s = -INFINITY;
        }
        w[r] = s;
        mx = fmaxf(mx, s);
    }
    // block max
    #pragma unroll
    for (int off = 16; off; off >>= 1)
        mx = fmaxf(mx, __shfl_xor_sync(0xffffffffu, mx, off));
    if (lane == 0) sred[warp] = mx;
    __syncthreads();
    if (tid < 32) {
        float m2 = (tid < 8) ? sred[tid] : -INFINITY;
        #pragma unroll
        for (int off = 4; off; off >>= 1)
            m2 = fmaxf(m2, __shfl_xor_sync(0xffffffffu, m2, off));
        if (tid == 0) sred[0] = m2;
    }
    __syncthreads();
    mx = sred[0];

    float sum = 0.f;
    #pragma unroll
    for (int r = 0; r < 8; r++) {
        float e = expf(w[r] - mx);   // expf(-inf - mx) = 0
        w[r] = e;
        sum += e;
    }
    __syncthreads();
    #pragma unroll
    for (int off = 16; off; off >>= 1)
        sum += __shfl_xor_sync(0xffffffffu, sum, off);
    if (lane == 0) sred[warp] = sum;
    __syncthreads();
    if (tid < 32) {
        float s2 = (tid < 8) ? sred[tid] : 0.f;
        #pragma unroll
        for (int off = 4; off; off >>= 1)
            s2 += __shfl_xor_sync(0xffffffffu, s2, off);
        if (tid == 0) sred[0] = s2;
    }
    __syncthreads();
    float inv = 1.0f / sred[0];

    #pragma unroll
    for (int r = 0; r < 8; r++) {
        int t = r * 256 + tid;
        align[(size_t)n * TT + t] = w[r] * inv;
    }
}

// ---------------------------------------------------------------------------
// K4: context partials: ctxpart[ts][n][e] = sum_{t in slice, t<len} a[n,t]*enc[n,t,e]
// grid (4 e-chunks, NB, 4 t-slices), 256 threads
// ---------------------------------------------------------------------------
__global__ void k_ctx(const float* __restrict__ enc, const float* __restrict__ align,
                      const int* __restrict__ lengths)
{
    int ec = blockIdx.x, n = blockIdx.y, ts = blockIdx.z;
    int tid = threadIdx.x;
    int len = lengths[n];
    int tbeg = ts * 512;
    int tend = min(len, tbeg + 512);

    __shared__ float sa[512];
    for (int i = tid; i < 512; i += 256) {
        int t = tbeg + i;
        sa[i] = (t < tend) ? align[(size_t)n * TT + t] : 0.f;
    }
    __syncthreads();

    int e = ec * 256 + tid;
    const float* eb = enc + (size_t)n * TT * DD + e;
    float acc = 0.f;
    int cnt = tend - tbeg;
    #pragma unroll 4
    for (int i = 0; i < cnt; i++)
        acc = fmaf(sa[i], eb[(size_t)(tbeg + i) * DD], acc);
    g_ctxpart[((size_t)ts * NB + n) * DD + e] = acc;
}

// K5: combine the 4 t-slice partials -> contexts (d_out head)
__global__ void k_comb(float* __restrict__ ctx)
{
    int idx = blockIdx.x * 256 + threadIdx.x;   // 0 .. NB*DD-1
    float s = 0.f;
    #pragma unroll
    for (int p = 0; p < 4; p++)
        s += g_ctxpart[(size_t)p * NB * DD + idx];
    ctx[idx] = s;
}

// ---------------------------------------------------------------------------
extern "C" void kernel_launch(void* const* d_in, const int* in_sizes, int n_in,
                              void* d_out, int out_size)
{
    const float* q    = (const float*)d_in[0];  // [32,1,1024]
    const float* enc  = (const float*)d_in[1];  // [32,2048,1024]
    const int*   len  = (const int*)  d_in[2];  // [32]
    const float* v    = (const float*)d_in[3];  // [1024]
    const float* Wq   = (const float*)d_in[4];  // [1024,1024]
    const float* Wk   = (const float*)d_in[5];  // [1024,1024]

    float* out       = (float*)d_out;
    float* out_ctx   = out;                 // [32,1024]
    float* out_align = out + NB * DD;       // [32,2048]

    k_pq     <<<dim3(NB, 4), 256>>>(q, Wq);
    k_weights<<<dim3(TT / BT, NB, NUB), 256>>>(enc, Wk, v, len);
    k_softmax<<<NB, 256>>>(len, out_align);
    k_ctx    <<<dim3(4, NB, 4), 256>>>(enc, out_align, len);
    k_comb   <<<NB * DD / 256, 256>>>(out_ctx);
}

// round 6
// speedup vs baseline: 2.3788x; 2.3788x over previous
#include <cuda_runtime.h>
#include <cuda_bf16.h>
#include <math.h>
#include <cstdint>

#define NB   32
#define TT   2048
#define DD   1024
#define NUB  8

// ---------------- device scratch (no allocs allowed) ----------------
__device__ float g_pq[NB * DD];                 // query projection
__device__ float g_wpart[NUB * NB * TT];        // per-u-block logit partials
__device__ __nv_bfloat16 g_wk_hi[DD * DD];      // Wk split hi
__device__ __nv_bfloat16 g_wk_lo[DD * DD];      // Wk split lo
__device__ float g_ctxpart[8 * NB * DD];        // context partials

// ---------------- helpers ----------------
__device__ __forceinline__ uint32_t smem_u32(const void* p) {
    uint32_t a;
    asm("{ .reg .u64 t; cvta.to.shared.u64 t, %1; cvt.u32.u64 %0, t; }" : "=r"(a) : "l"(p));
    return a;
}
__device__ __forceinline__ void ldsm4(uint32_t* r, uint32_t addr) {
    asm volatile("ldmatrix.sync.aligned.m8n8.x4.shared.b16 {%0,%1,%2,%3}, [%4];"
        : "=r"(r[0]), "=r"(r[1]), "=r"(r[2]), "=r"(r[3]) : "r"(addr));
}
__device__ __forceinline__ void mma16816(float* d, const uint32_t* a, const uint32_t* b) {
    asm volatile("mma.sync.aligned.m16n8k16.row.col.f32.bf16.bf16.f32 "
        "{%0,%1,%2,%3}, {%4,%5,%6,%7}, {%8,%9}, {%0,%1,%2,%3};"
        : "+f"(d[0]), "+f"(d[1]), "+f"(d[2]), "+f"(d[3])
        : "r"(a[0]), "r"(a[1]), "r"(a[2]), "r"(a[3]), "r"(b[0]), "r"(b[1]));
}
#define CP_ASYNC16(sts, g) \
    asm volatile("cp.async.cg.shared.global [%0], [%1], 16;" :: "r"(sts), "l"(g) : "memory")
#define CP_COMMIT() asm volatile("cp.async.commit_group;" ::: "memory")
#define CP_WAIT0()  asm volatile("cp.async.wait_group 0;" ::: "memory")

__device__ __forceinline__ uint2 pack_hi4(float4 e) {
    __nv_bfloat16 h0 = __float2bfloat16(e.x), h1 = __float2bfloat16(e.y);
    __nv_bfloat16 h2 = __float2bfloat16(e.z), h3 = __float2bfloat16(e.w);
    return make_uint2((uint32_t)__bfloat16_as_ushort(h0) | ((uint32_t)__bfloat16_as_ushort(h1) << 16),
                      (uint32_t)__bfloat16_as_ushort(h2) | ((uint32_t)__bfloat16_as_ushort(h3) << 16));
}
__device__ __forceinline__ uint2 pack_lo4(float4 e) {
    __nv_bfloat16 h0 = __float2bfloat16(e.x), h1 = __float2bfloat16(e.y);
    __nv_bfloat16 h2 = __float2bfloat16(e.z), h3 = __float2bfloat16(e.w);
    __nv_bfloat16 l0 = __float2bfloat16(e.x - __bfloat162float(h0));
    __nv_bfloat16 l1 = __float2bfloat16(e.y - __bfloat162float(h1));
    __nv_bfloat16 l2 = __float2bfloat16(e.z - __bfloat162float(h2));
    __nv_bfloat16 l3 = __float2bfloat16(e.w - __bfloat162float(h3));
    return make_uint2((uint32_t)__bfloat16_as_ushort(l0) | ((uint32_t)__bfloat16_as_ushort(l1) << 16),
                      (uint32_t)__bfloat16_as_ushort(l2) | ((uint32_t)__bfloat16_as_ushort(l3) << 16));
}

// ---------------- smem layout for k_weights_mma ----------------
#define KC        64                   // K per chunk
#define ROWB      144                  // bytes per smem row: 128 data + 16 pad
#define TILEB     (128 * ROWB)         // 18432
#define OFF_AH    0
#define OFF_AL    TILEB
#define OFF_BH    (2 * TILEB)
#define OFF_BL    (3 * TILEB)
#define BUFB      (4 * TILEB)          // 73728
#define OFF_PQ    (2 * BUFB)           // 147456
#define OFF_V     (OFF_PQ + 512)
#define OFF_RED   (OFF_V + 512)        // 256 floats
#define SMEMB     (OFF_RED + 1024)     // 149504

// ---------------------------------------------------------------------------
// K0: split Wk into bf16 hi/lo
// ---------------------------------------------------------------------------
__global__ void k_split(const float* __restrict__ Wk)
{
    int i = (blockIdx.x * 256 + threadIdx.x) * 4;
    #pragma unroll
    for (int j = 0; j < 4; j++) {
        float x = Wk[i + j];
        __nv_bfloat16 h = __float2bfloat16(x);
        g_wk_hi[i + j] = h;
        g_wk_lo[i + j] = __float2bfloat16(x - __bfloat162float(h));
    }
}

// ---------------------------------------------------------------------------
// K1: pq[n,u] = q[n,:] . Wq[u,:]
// ---------------------------------------------------------------------------
__global__ void k_pq(const float* __restrict__ q, const float* __restrict__ Wq)
{
    int n = blockIdx.x;
    __shared__ float sq[DD];
    int tid = threadIdx.x;
    for (int i = tid; i < DD; i += 256) sq[i] = q[n * DD + i];
    __syncthreads();
    int warp = tid >> 5, lane = tid & 31;
    int ubase = blockIdx.y * 256 + warp * 32;
    for (int uu = 0; uu < 32; uu++) {
        int u = ubase + uu;
        const float* wr = Wq + (size_t)u * DD;
        float s = 0.f;
        #pragma unroll 8
        for (int m = 0; m < 32; m++) s = fmaf(sq[lane + 32 * m], wr[lane + 32 * m], s);
        #pragma unroll
        for (int off = 16; off; off >>= 1) s += __shfl_xor_sync(0xffffffffu, s, off);
        if (lane == 0) g_pq[n * DD + u] = s;
    }
}

// ---------------------------------------------------------------------------
// K2: split-bf16 GEMM via mma.sync (HMMA) + tanh/v epilogue -> g_wpart
// grid (16 t-blocks, 32 n, 8 u-blocks), 256 threads, warp tile 32x64
// ---------------------------------------------------------------------------
__global__ __launch_bounds__(256, 1)
void k_weights_mma(const float* __restrict__ enc, const float* __restrict__ v,
                   const int* __restrict__ lengths)
{
    int tb = blockIdx.x, n = blockIdx.y, ub = blockIdx.z;
    int len = lengths[n];
    int t0 = tb * 128;
    if (t0 >= len) return;

    extern __shared__ char smem[];
    uint32_t sb = smem_u32(smem);
    float* spq  = (float*)(smem + OFF_PQ);
    float* sv   = (float*)(smem + OFF_V);
    float* sred = (float*)(smem + OFF_RED);

    int tid = threadIdx.x, lane = tid & 31, wid = tid >> 5;
    int wm = wid >> 1, wn = wid & 1;    // warp grid 4 (m) x 2 (n)

    if (tid < 128) {
        spq[tid] = g_pq[n * DD + ub * 128 + tid];
        sv[tid]  = v[ub * 128 + tid];
    }

    const float* encb = enc + ((size_t)n * TT + t0) * DD;
    const __nv_bfloat16* bhg = g_wk_hi + (size_t)ub * 128 * DD;
    const __nv_bfloat16* blg = g_wk_lo + (size_t)ub * 128 * DD;

    float acc[2][8][4];
    #pragma unroll
    for (int mi = 0; mi < 2; mi++)
        #pragma unroll
        for (int nj = 0; nj < 8; nj++)
            #pragma unroll
            for (int c = 0; c < 4; c++) acc[mi][nj][c] = 0.f;

    // per-thread staging coords
    // A: idx = it*256+tid -> row = idx>>4 (0..127), u4 = idx&15 (4 floats each)
    // B: idx = it*256+tid -> row = idx>>3 (0..127), u16 = idx&7 (16B each)

    // ---- prologue: stage chunk 0 into buffer 0
    {
        char* b0 = smem;
        #pragma unroll
        for (int it = 0; it < 8; it++) {
            int idx = it * 256 + tid, row = idx >> 4, u4 = idx & 15;
            float4 e = *(const float4*)(encb + (size_t)row * DD + u4 * 4);
            *(uint2*)(b0 + OFF_AH + row * ROWB + u4 * 8) = pack_hi4(e);
            *(uint2*)(b0 + OFF_AL + row * ROWB + u4 * 8) = pack_lo4(e);
        }
        #pragma unroll
        for (int it = 0; it < 4; it++) {
            int idx = it * 256 + tid, row = idx >> 3, u16 = idx & 7;
            CP_ASYNC16(sb + OFF_BH + row * ROWB + u16 * 16, bhg + (size_t)row * DD + u16 * 8);
            CP_ASYNC16(sb + OFF_BL + row * ROWB + u16 * 16, blg + (size_t)row * DD + u16 * 8);
        }
        CP_COMMIT(); CP_WAIT0();
    }
    __syncthreads();

    for (int c = 0; c < 16; c++) {
        uint32_t cur = sb + (uint32_t)(c & 1) * BUFB;
        char*    nxtp = smem + ((c + 1) & 1) * BUFB;
        uint32_t nxt  = sb + (uint32_t)((c + 1) & 1) * BUFB;
        int kcn = (c + 1) * KC;
        bool pf = (c < 15);

        float4 areg[8];
        if (pf) {
            #pragma unroll
            for (int it = 0; it < 8; it++) {
                int idx = it * 256 + tid, row = idx >> 4, u4 = idx & 15;
                areg[it] = *(const float4*)(encb + (size_t)row * DD + kcn + u4 * 4);
            }
            #pragma unroll
            for (int it = 0; it < 4; it++) {
                int idx = it * 256 + tid, row = idx >> 3, u16 = idx & 7;
                CP_ASYNC16(nxt + OFF_BH + row * ROWB + u16 * 16,
                           bhg + (size_t)row * DD + kcn + u16 * 8);
                CP_ASYNC16(nxt + OFF_BL + row * ROWB + u16 * 16,
                           blg + (size_t)row * DD + kcn + u16 * 8);
            }
            CP_COMMIT();
        }

        // ---- consume current buffer: 4 k-steps of 16
        #pragma unroll
        for (int ks = 0; ks < 4; ks++) {
            uint32_t aH[2][4], aL[2][4], bH[8][2], bL[8][2];
            #pragma unroll
            for (int mi = 0; mi < 2; mi++) {
                int row = wm * 32 + mi * 16 + (lane & 15);
                uint32_t byte = (uint32_t)(row * ROWB + ks * 32 + ((lane >> 4) << 4));
                ldsm4(aH[mi], cur + OFF_AH + byte);
                ldsm4(aL[mi], cur + OFF_AL + byte);
            }
            #pragma unroll
            for (int p = 0; p < 4; p++) {
                int row = wn * 64 + p * 16 + (lane & 7) + ((lane >> 4) << 3);
                uint32_t byte = (uint32_t)(row * ROWB + ks * 32 + (((lane >> 3) & 1) << 4));
                uint32_t r[4];
                ldsm4(r, cur + OFF_BH + byte);
                bH[2 * p][0] = r[0]; bH[2 * p][1] = r[1];
                bH[2 * p + 1][0] = r[2]; bH[2 * p + 1][1] = r[3];
                ldsm4(r, cur + OFF_BL + byte);
                bL[2 * p][0] = r[0]; bL[2 * p][1] = r[1];
                bL[2 * p + 1][0] = r[2]; bL[2 * p + 1][1] = r[3];
            }
            #pragma unroll
            for (int mi = 0; mi < 2; mi++)
                #pragma unroll
                for (int nj = 0; nj < 8; nj++) {
                    mma16816(acc[mi][nj], aH[mi], bH[nj]);
                    mma16816(acc[mi][nj], aH[mi], bL[nj]);
                    mma16816(acc[mi][nj], aL[mi], bH[nj]);
                }
        }

        if (pf) {
            #pragma unroll
            for (int it = 0; it < 8; it++) {
                int idx = it * 256 + tid, row = idx >> 4, u4 = idx & 15;
                *(uint2*)(nxtp + OFF_AH + row * ROWB + u4 * 8) = pack_hi4(areg[it]);
                *(uint2*)(nxtp + OFF_AL + row * ROWB + u4 * 8) = pack_lo4(areg[it]);
            }
            CP_WAIT0();
        }
        __syncthreads();
    }

    // ---- epilogue: tanh(acc + pq)*v, reduce over u (cols)
    float rs[2][2] = {{0.f, 0.f}, {0.f, 0.f}};
    #pragma unroll
    for (int mi = 0; mi < 2; mi++)
        #pragma unroll
        for (int nj = 0; nj < 8; nj++) {
            int cu = wn * 64 + nj * 8 + (lane & 3) * 2;
            float p0 = spq[cu], p1 = spq[cu + 1];
            float v0 = sv[cu],  v1 = sv[cu + 1];
            rs[mi][0] += tanhf(acc[mi][nj][0] + p0) * v0 + tanhf(acc[mi][nj][1] + p1) * v1;
            rs[mi][1] += tanhf(acc[mi][nj][2] + p0) * v0 + tanhf(acc[mi][nj][3] + p1) * v1;
        }
    #pragma unroll
    for (int off = 1; off <= 2; off <<= 1) {
        #pragma unroll
        for (int mi = 0; mi < 2; mi++) {
            rs[mi][0] += __shfl_xor_sync(0xffffffffu, rs[mi][0], off);
            rs[mi][1] += __shfl_xor_sync(0xffffffffu, rs[mi][1], off);
        }
    }
    if ((lane & 3) == 0) {
        int tg = lane >> 2;
        #pragma unroll
        for (int mi = 0; mi < 2; mi++) {
            int r0 = wm * 32 + mi * 16 + tg;
            sred[wn * 128 + r0]     = rs[mi][0];
            sred[wn * 128 + r0 + 8] = rs[mi][1];
        }
    }
    __syncthreads();
    if (tid < 128) {
        float part = sred[tid] + sred[128 + tid];
        g_wpart[((size_t)ub * NB + n) * TT + t0 + tid] = part;
    }
}

// ---------------------------------------------------------------------------
// K3: sum u-block partials, mask, stable softmax -> alignments
// ---------------------------------------------------------------------------
__global__ void k_softmax(const int* __restrict__ lengths, float* __restrict__ align)
{
    int n = blockIdx.x, tid = threadIdx.x;
    int len = lengths[n];
    int warp = tid >> 5, lane = tid & 31;
    __shared__ float sredb[8];

    float w[8];
    float mx = -INFINITY;
    #pragma unroll
    for (int r = 0; r < 8; r++) {
        int t = r * 256 + tid;
        float s;
        if (t < len) {
            s = 0.f;
            #pragma unroll
            for (int p = 0; p < NUB; p++)
                s += g_wpart[((size_t)p * NB + n) * TT + t];
        } else {
            s = -INFINITY;
        }
        w[r] = s;
        mx = fmaxf(mx, s);
    }
    #pragma unroll
    for (int off = 16; off; off >>= 1) mx = fmaxf(mx, __shfl_xor_sync(0xffffffffu, mx, off));
    if (lane == 0) sredb[warp] = mx;
    __syncthreads();
    if (tid < 32) {
        float m2 = (tid < 8) ? sredb[tid] : -INFINITY;
        #pragma unroll
        for (int off = 4; off; off >>= 1) m2 = fmaxf(m2, __shfl_xor_sync(0xffffffffu, m2, off));
        if (tid == 0) sredb[0] = m2;
    }
    __syncthreads();
    mx = sredb[0];

    float sum = 0.f;
    #pragma unroll
    for (int r = 0; r < 8; r++) { float e = expf(w[r] - mx); w[r] = e; sum += e; }
    __syncthreads();
    #pragma unroll
    for (int off = 16; off; off >>= 1) sum += __shfl_xor_sync(0xffffffffu, sum, off);
    if (lane == 0) sredb[warp] = sum;
    __syncthreads();
    if (tid < 32) {
        float s2 = (tid < 8) ? sredb[tid] : 0.f;
        #pragma unroll
        for (int off = 4; off; off >>= 1) s2 += __shfl_xor_sync(0xffffffffu, s2, off);
        if (tid == 0) sredb[0] = s2;
    }
    __syncthreads();
    float inv = 1.0f / sredb[0];
    #pragma unroll
    for (int r = 0; r < 8; r++) {
        int t = r * 256 + tid;
        align[(size_t)n * TT + t] = w[r] * inv;
    }
}

// ---------------------------------------------------------------------------
// K4: context partials over 8 t-slices of 256
// ---------------------------------------------------------------------------
__global__ void k_ctx(const float* __restrict__ enc, const float* __restrict__ align,
                      const int* __restrict__ lengths)
{
    int ec = blockIdx.x, n = blockIdx.y, ts = blockIdx.z;
    int tid = threadIdx.x;
    int len = lengths[n];
    int tbeg = ts * 256;
    int tend = min(len, tbeg + 256);

    __shared__ float sa[256];
    {
        int t = tbeg + tid;
        sa[tid] = (t < tend) ? align[(size_t)n * TT + t] : 0.f;
    }
    __syncthreads();

    int e = ec * 256 + tid;
    const float* eb = enc + (size_t)n * TT * DD + e;
    float accv = 0.f;
    int cnt = tend - tbeg;
    #pragma unroll 8
    for (int i = 0; i < cnt; i++)
        accv = fmaf(sa[i], eb[(size_t)(tbeg + i) * DD], accv);
    g_ctxpart[((size_t)ts * NB + n) * DD + e] = accv;
}

__global__ void k_comb(float* __restrict__ ctx)
{
    int idx = blockIdx.x * 256 + threadIdx.x;
    float s = 0.f;
    #pragma unroll
    for (int p = 0; p < 8; p++) s += g_ctxpart[(size_t)p * NB * DD + idx];
    ctx[idx] = s;
}

// ---------------------------------------------------------------------------
extern "C" void kernel_launch(void* const* d_in, const int* in_sizes, int n_in,
                              void* d_out, int out_size)
{
    const float* q   = (const float*)d_in[0];
    const float* enc = (const float*)d_in[1];
    const int*   len = (const int*)  d_in[2];
    const float* v   = (const float*)d_in[3];
    const float* Wq  = (const float*)d_in[4];
    const float* Wk  = (const float*)d_in[5];

    float* out       = (float*)d_out;
    float* out_ctx   = out;
    float* out_align = out + NB * DD;

    cudaFuncSetAttribute(k_weights_mma, cudaFuncAttributeMaxDynamicSharedMemorySize, SMEMB);

    k_split      <<<DD * DD / 1024, 256>>>(Wk);
    k_pq         <<<dim3(NB, 4), 256>>>(q, Wq);
    k_weights_mma<<<dim3(TT / 128, NB, NUB), 256, SMEMB>>>(enc, v, len);
    k_softmax    <<<NB, 256>>>(len, out_align);
    k_ctx        <<<dim3(4, NB, 8), 256>>>(enc, out_align, len);
    k_comb       <<<NB * DD / 256, 256>>>(out_ctx);
}

// round 11
// speedup vs baseline: 2.3931x; 1.0060x over previous
#include <cuda_runtime.h>
#include <cuda_bf16.h>
#include <math.h>
#include <cstdint>

#define NB   32
#define TT   2048
#define DD   1024
#define NUB  8

// ---------------- device scratch (no allocs allowed) ----------------
__device__ float g_pq[NB * DD];                 // query projection
__device__ float g_wpart[NUB * NB * TT];        // per-u-block logit partials
__device__ __nv_bfloat16 g_wk_hi[DD * DD];      // Wk split hi
__device__ __nv_bfloat16 g_wk_lo[DD * DD];      // Wk split lo
__device__ __nv_bfloat16 g_enc_hi[(size_t)NB * TT * DD];  // enc split hi (128MB)
__device__ __nv_bfloat16 g_enc_lo[(size_t)NB * TT * DD];  // enc split lo (128MB)
__device__ float g_ctxpart[8 * NB * DD];        // context partials

// ---------------- helpers ----------------
__device__ __forceinline__ uint32_t smem_u32(const void* p) {
    uint32_t a;
    asm("{ .reg .u64 t; cvta.to.shared.u64 t, %1; cvt.u32.u64 %0, t; }" : "=r"(a) : "l"(p));
    return a;
}
__device__ __forceinline__ void ldsm4(uint32_t* r, uint32_t addr) {
    asm volatile("ldmatrix.sync.aligned.m8n8.x4.shared.b16 {%0,%1,%2,%3}, [%4];"
        : "=r"(r[0]), "=r"(r[1]), "=r"(r[2]), "=r"(r[3]) : "r"(addr));
}
__device__ __forceinline__ void mma16816(float* d, const uint32_t* a, const uint32_t* b) {
    asm volatile("mma.sync.aligned.m16n8k16.row.col.f32.bf16.bf16.f32 "
        "{%0,%1,%2,%3}, {%4,%5,%6,%7}, {%8,%9}, {%0,%1,%2,%3};"
        : "+f"(d[0]), "+f"(d[1]), "+f"(d[2]), "+f"(d[3])
        : "r"(a[0]), "r"(a[1]), "r"(a[2]), "r"(a[3]), "r"(b[0]), "r"(b[1]));
}
#define CP_ASYNC16(sts, g) \
    asm volatile("cp.async.cg.shared.global [%0], [%1], 16;" :: "r"(sts), "l"(g) : "memory")
#define CP_COMMIT() asm volatile("cp.async.commit_group;" ::: "memory")
#define CP_WAIT0()  asm volatile("cp.async.wait_group 0;" ::: "memory")

// ---------------- smem layout for k_weights_mma ----------------
#define KC        64                   // K per chunk
#define ROWB      144                  // bytes per smem row: 128 data + 16 pad
#define TILEB     (128 * ROWB)         // 18432
#define OFF_AH    0
#define OFF_AL    TILEB
#define OFF_BH    (2 * TILEB)
#define OFF_BL    (3 * TILEB)
#define BUFB      (4 * TILEB)          // 73728
#define OFF_PQ    (2 * BUFB)           // 147456
#define OFF_V     (OFF_PQ + 512)
#define OFF_RED   (OFF_V + 512)        // 256 floats
#define SMEMB     (OFF_RED + 1024)     // 149504

// ---------------------------------------------------------------------------
// K0a: split Wk into bf16 hi/lo
// ---------------------------------------------------------------------------
__global__ void k_split(const float* __restrict__ Wk)
{
    int i = (blockIdx.x * 256 + threadIdx.x) * 4;
    #pragma unroll
    for (int j = 0; j < 4; j++) {
        float x = Wk[i + j];
        __nv_bfloat16 h = __float2bfloat16(x);
        g_wk_hi[i + j] = h;
        g_wk_lo[i + j] = __float2bfloat16(x - __bfloat162float(h));
    }
}

// ---------------------------------------------------------------------------
// K0b: split enc into bf16 hi/lo (masked: skip fully-invalid 32-row tiles)
// grid (TT/32, NB), 256 threads
// ---------------------------------------------------------------------------
__global__ void k_enc_split(const float* __restrict__ enc, const int* __restrict__ lengths)
{
    int n = blockIdx.y;
    int t0 = blockIdx.x * 32;
    if (t0 >= lengths[n]) return;
    size_t base = ((size_t)n * TT + t0) * DD;
    #pragma unroll 4
    for (int i = threadIdx.x; i < 32 * DD / 4; i += 256) {
        float4 e = *(const float4*)(enc + base + (size_t)i * 4);
        __nv_bfloat16 h0 = __float2bfloat16(e.x), h1 = __float2bfloat16(e.y);
        __nv_bfloat16 h2 = __float2bfloat16(e.z), h3 = __float2bfloat16(e.w);
        uint2 hi = make_uint2(
            (uint32_t)__bfloat16_as_ushort(h0) | ((uint32_t)__bfloat16_as_ushort(h1) << 16),
            (uint32_t)__bfloat16_as_ushort(h2) | ((uint32_t)__bfloat16_as_ushort(h3) << 16));
        __nv_bfloat16 l0 = __float2bfloat16(e.x - __bfloat162float(h0));
        __nv_bfloat16 l1 = __float2bfloat16(e.y - __bfloat162float(h1));
        __nv_bfloat16 l2 = __float2bfloat16(e.z - __bfloat162float(h2));
        __nv_bfloat16 l3 = __float2bfloat16(e.w - __bfloat162float(h3));
        uint2 lo = make_uint2(
            (uint32_t)__bfloat16_as_ushort(l0) | ((uint32_t)__bfloat16_as_ushort(l1) << 16),
            (uint32_t)__bfloat16_as_ushort(l2) | ((uint32_t)__bfloat16_as_ushort(l3) << 16));
        *(uint2*)(g_enc_hi + base + (size_t)i * 4) = hi;
        *(uint2*)(g_enc_lo + base + (size_t)i * 4) = lo;
    }
}

// ---------------------------------------------------------------------------
// K1: pq[n,u] = q[n,:] . Wq[u,:]
// ---------------------------------------------------------------------------
__global__ void k_pq(const float* __restrict__ q, const float* __restrict__ Wq)
{
    int n = blockIdx.x;
    __shared__ float sq[DD];
    int tid = threadIdx.x;
    for (int i = tid; i < DD; i += 256) sq[i] = q[n * DD + i];
    __syncthreads();
    int warp = tid >> 5, lane = tid & 31;
    int ubase = blockIdx.y * 256 + warp * 32;
    for (int uu = 0; uu < 32; uu++) {
        int u = ubase + uu;
        const float* wr = Wq + (size_t)u * DD;
        float s = 0.f;
        #pragma unroll 8
        for (int m = 0; m < 32; m++) s = fmaf(sq[lane + 32 * m], wr[lane + 32 * m], s);
        #pragma unroll
        for (int off = 16; off; off >>= 1) s += __shfl_xor_sync(0xffffffffu, s, off);
        if (lane == 0) g_pq[n * DD + u] = s;
    }
}

// ---------------------------------------------------------------------------
// K2: split-bf16 GEMM via mma.sync (HMMA), all-async staging -> g_wpart
// grid (16 t-blocks, 32 n, 8 u-blocks), 256 threads, warp tile 32x64
// ---------------------------------------------------------------------------
__global__ __launch_bounds__(256, 1)
void k_weights_mma(const float* __restrict__ v, const int* __restrict__ lengths)
{
    int tb = blockIdx.x, n = blockIdx.y, ub = blockIdx.z;
    int len = lengths[n];
    int t0 = tb * 128;
    if (t0 >= len) return;

    extern __shared__ char smem[];
    uint32_t sb = smem_u32(smem);
    float* spq  = (float*)(smem + OFF_PQ);
    float* sv   = (float*)(smem + OFF_V);
    float* sred = (float*)(smem + OFF_RED);

    int tid = threadIdx.x, lane = tid & 31, wid = tid >> 5;
    int wm = wid >> 1, wn = wid & 1;    // warp grid 4 (m) x 2 (n)

    if (tid < 128) {
        spq[tid] = g_pq[n * DD + ub * 128 + tid];
        sv[tid]  = v[ub * 128 + tid];
    }

    const __nv_bfloat16* ahg = g_enc_hi + ((size_t)n * TT + t0) * DD;
    const __nv_bfloat16* alg = g_enc_lo + ((size_t)n * TT + t0) * DD;
    const __nv_bfloat16* bhg = g_wk_hi + (size_t)ub * 128 * DD;
    const __nv_bfloat16* blg = g_wk_lo + (size_t)ub * 128 * DD;

    float acc[2][8][4];
    #pragma unroll
    for (int mi = 0; mi < 2; mi++)
        #pragma unroll
        for (int nj = 0; nj < 8; nj++)
            #pragma unroll
            for (int c = 0; c < 4; c++) acc[mi][nj][c] = 0.f;

    // staging: per array 128 rows x 64 bf16 = 1024 x 16B units; 4/thread
    int srow = tid >> 3;           // 0..31 base row group (x4)
    int su   = tid & 7;            // 16B unit in row
    // each thread covers rows srow, srow+32, srow+64, srow+96

    // ---- prologue: stage chunk 0 into buffer 0
    #pragma unroll
    for (int it = 0; it < 4; it++) {
        int row = srow + it * 32;
        size_t go = (size_t)row * DD + su * 8;
        uint32_t so = (uint32_t)(row * ROWB + su * 16);
        CP_ASYNC16(sb + OFF_AH + so, ahg + go);
        CP_ASYNC16(sb + OFF_AL + so, alg + go);
        CP_ASYNC16(sb + OFF_BH + so, bhg + go);
        CP_ASYNC16(sb + OFF_BL + so, blg + go);
    }
    CP_COMMIT(); CP_WAIT0();
    __syncthreads();

    for (int c = 0; c < 16; c++) {
        uint32_t cur = sb + (uint32_t)(c & 1) * BUFB;
        uint32_t nxt = sb + (uint32_t)((c + 1) & 1) * BUFB;
        int kcn = (c + 1) * KC;
        bool pf = (c < 15);

        if (pf) {
            #pragma unroll
            for (int it = 0; it < 4; it++) {
                int row = srow + it * 32;
                size_t go = (size_t)row * DD + kcn + su * 8;
                uint32_t so = (uint32_t)(row * ROWB + su * 16);
                CP_ASYNC16(nxt + OFF_AH + so, ahg + go);
                CP_ASYNC16(nxt + OFF_AL + so, alg + go);
                CP_ASYNC16(nxt + OFF_BH + so, bhg + go);
                CP_ASYNC16(nxt + OFF_BL + so, blg + go);
            }
            CP_COMMIT();
        }

        // ---- consume current buffer: 4 k-steps of 16
        #pragma unroll
        for (int ks = 0; ks < 4; ks++) {
            uint32_t aH[2][4], aL[2][4], bH[8][2], bL[8][2];
            #pragma unroll
            for (int mi = 0; mi < 2; mi++) {
                int row = wm * 32 + mi * 16 + (lane & 15);
                uint32_t byte = (uint32_t)(row * ROWB + ks * 32 + ((lane >> 4) << 4));
                ldsm4(aH[mi], cur + OFF_AH + byte);
                ldsm4(aL[mi], cur + OFF_AL + byte);
            }
            #pragma unroll
            for (int p = 0; p < 4; p++) {
                int row = wn * 64 + p * 16 + (lane & 7) + ((lane >> 4) << 3);
                uint32_t byte = (uint32_t)(row * ROWB + ks * 32 + (((lane >> 3) & 1) << 4));
                uint32_t r[4];
                ldsm4(r, cur + OFF_BH + byte);
                bH[2 * p][0] = r[0]; bH[2 * p][1] = r[1];
                bH[2 * p + 1][0] = r[2]; bH[2 * p + 1][1] = r[3];
                ldsm4(r, cur + OFF_BL + byte);
                bL[2 * p][0] = r[0]; bL[2 * p][1] = r[1];
                bL[2 * p + 1][0] = r[2]; bL[2 * p + 1][1] = r[3];
            }
            #pragma unroll
            for (int mi = 0; mi < 2; mi++)
                #pragma unroll
                for (int nj = 0; nj < 8; nj++) {
                    mma16816(acc[mi][nj], aH[mi], bH[nj]);
                    mma16816(acc[mi][nj], aH[mi], bL[nj]);
                    mma16816(acc[mi][nj], aL[mi], bH[nj]);
                }
        }

        if (pf) CP_WAIT0();
        __syncthreads();
    }

    // ---- epilogue: tanh(acc + pq)*v, reduce over u (cols)
    float rs[2][2] = {{0.f, 0.f}, {0.f, 0.f}};
    #pragma unroll
    for (int mi = 0; mi < 2; mi++)
        #pragma unroll
        for (int nj = 0; nj < 8; nj++) {
            int cu = wn * 64 + nj * 8 + (lane & 3) * 2;
            float p0 = spq[cu], p1 = spq[cu + 1];
            float v0 = sv[cu],  v1 = sv[cu + 1];
            rs[mi][0] += tanhf(acc[mi][nj][0] + p0) * v0 + tanhf(acc[mi][nj][1] + p1) * v1;
            rs[mi][1] += tanhf(acc[mi][nj][2] + p0) * v0 + tanhf(acc[mi][nj][3] + p1) * v1;
        }
    #pragma unroll
    for (int off = 1; off <= 2; off <<= 1) {
        #pragma unroll
        for (int mi = 0; mi < 2; mi++) {
            rs[mi][0] += __shfl_xor_sync(0xffffffffu, rs[mi][0], off);
            rs[mi][1] += __shfl_xor_sync(0xffffffffu, rs[mi][1], off);
        }
    }
    if ((lane & 3) == 0) {
        int tg = lane >> 2;
        #pragma unroll
        for (int mi = 0; mi < 2; mi++) {
            int r0 = wm * 32 + mi * 16 + tg;
            sred[wn * 128 + r0]     = rs[mi][0];
            sred[wn * 128 + r0 + 8] = rs[mi][1];
        }
    }
    __syncthreads();
    if (tid < 128) {
        float part = sred[tid] + sred[128 + tid];
        g_wpart[((size_t)ub * NB + n) * TT + t0 + tid] = part;
    }
}

// ---------------------------------------------------------------------------
// K3: sum u-block partials, mask, stable softmax -> alignments
// ---------------------------------------------------------------------------
__global__ void k_softmax(const int* __restrict__ lengths, float* __restrict__ align)
{
    int n = blockIdx.x, tid = threadIdx.x;
    int len = lengths[n];
    int warp = tid >> 5, lane = tid & 31;
    __shared__ float sredb[8];

    float w[8];
    float mx = -INFINITY;
    #pragma unroll
    for (int r = 0; r < 8; r++) {
        int t = r * 256 + tid;
        float s;
        if (t < len) {
            s = 0.f;
            #pragma unroll
            for (int p = 0; p < NUB; p++)
                s += g_wpart[((size_t)p * NB + n) * TT + t];
        } else {
            s = -INFINITY;
        }
        w[r] = s;
        mx = fmaxf(mx, s);
    }
    #pragma unroll
    for (int off = 16; off; off >>= 1) mx = fmaxf(mx, __shfl_xor_sync(0xffffffffu, mx, off));
    if (lane == 0) sredb[warp] = mx;
    __syncthreads();
    if (tid < 32) {
        float m2 = (tid < 8) ? sredb[tid] : -INFINITY;
        #pragma unroll
        for (int off = 4; off; off >>= 1) m2 = fmaxf(m2, __shfl_xor_sync(0xffffffffu, m2, off));
        if (tid == 0) sredb[0] = m2;
    }
    __syncthreads();
    mx = sredb[0];

    float sum = 0.f;
    #pragma unroll
    for (int r = 0; r < 8; r++) { float e = expf(w[r] - mx); w[r] = e; sum += e; }
    __syncthreads();
    #pragma unroll
    for (int off = 16; off; off >>= 1) sum += __shfl_xor_sync(0xffffffffu, sum, off);
    if (lane == 0) sredb[warp] = sum;
    __syncthreads();
    if (tid < 32) {
        float s2 = (tid < 8) ? sredb[tid] : 0.f;
        #pragma unroll
        for (int off = 4; off; off >>= 1) s2 += __shfl_xor_sync(0xffffffffu, s2, off);
        if (tid == 0) sredb[0] = s2;
    }
    __syncthreads();
    float inv = 1.0f / sredb[0];
    #pragma unroll
    for (int r = 0; r < 8; r++) {
        int t = r * 256 + tid;
        align[(size_t)n * TT + t] = w[r] * inv;
    }
}

// ---------------------------------------------------------------------------
// K4: context partials over 8 t-slices of 256
// ---------------------------------------------------------------------------
__global__ void k_ctx(const float* __restrict__ enc, const float* __restrict__ align,
                      const int* __restrict__ lengths)
{
    int ec = blockIdx.x, n = blockIdx.y, ts = blockIdx.z;
    int tid = threadIdx.x;
    int len = lengths[n];
    int tbeg = ts * 256;
    int tend = min(len, tbeg + 256);

    __shared__ float sa[256];
    {
        int t = tbeg + tid;
        sa[tid] = (t < tend) ? align[(size_t)n * TT + t] : 0.f;
    }
    __syncthreads();

    int e = ec * 256 + tid;
    const float* eb = enc + (size_t)n * TT * DD + e;
    float accv = 0.f;
    int cnt = tend - tbeg;
    #pragma unroll 8
    for (int i = 0; i < cnt; i++)
        accv = fmaf(sa[i], eb[(size_t)(tbeg + i) * DD], accv);
    g_ctxpart[((size_t)ts * NB + n) * DD + e] = accv;
}

__global__ void k_comb(float* __restrict__ ctx)
{
    int idx = blockIdx.x * 256 + threadIdx.x;
    float s = 0.f;
    #pragma unroll
    for (int p = 0; p < 8; p++) s += g_ctxpart[(size_t)p * NB * DD + idx];
    ctx[idx] = s;
}

// ---------------------------------------------------------------------------
extern "C" void kernel_launch(void* const* d_in, const int* in_sizes, int n_in,
                              void* d_out, int out_size)
{
    const float* q   = (const float*)d_in[0];
    const float* enc = (const float*)d_in[1];
    const int*   len = (const int*)  d_in[2];
    const float* v   = (const float*)d_in[3];
    const float* Wq  = (const float*)d_in[4];
    const float* Wk  = (const float*)d_in[5];

    float* out       = (float*)d_out;
    float* out_ctx   = out;
    float* out_align = out + NB * DD;

    cudaFuncSetAttribute(k_weights_mma, cudaFuncAttributeMaxDynamicSharedMemorySize, SMEMB);

    k_split      <<<DD * DD / 1024, 256>>>(Wk);
    k_enc_split  <<<dim3(TT / 32, NB), 256>>>(enc, len);
    k_pq         <<<dim3(NB, 4), 256>>>(q, Wq);
    k_weights_mma<<<dim3(TT / 128, NB, NUB), 256, SMEMB>>>(v, len);
    k_softmax    <<<NB, 256>>>(len, out_align);
    k_ctx        <<<dim3(4, NB, 8), 256>>>(enc, out_align, len);
    k_comb       <<<NB * DD / 256, 256>>>(out_ctx);
}